// round 6
// baseline (speedup 1.0000x reference)
#include <cuda_runtime.h>
#include <cuda_bf16.h>

// Problem constants (fixed by the dataset)
#define BB 16
#define TT 32641
#define EE 128
#define LL (TT + EE - 1)            // 32768 groups (power of two)
#define RR 32                       // rows per tile (high occupancy)
#define TILES ((TT + RR - 1) / RR)  // 1021
#define TPC 4                       // tiles per chunk (fine granularity, small tail)
#define CHUNKS ((TILES + TPC - 1) / TPC) // 256

// Scratch: per-(batch, group) partial sums (4 MB). Zero at module load;
// finalize re-zeroes after reading, so every run/replay starts clean.
__device__ float g_S1[BB * LL];
__device__ float g_S2[BB * LL];
__device__ float g_acc;             // cross-block accumulator (reset each run)
__device__ unsigned int g_cnt;      // ticket counter (reset each run)

// ---------------------------------------------------------------------------
// Kernel 1: software-pipelined anti-diagonal partial sums.
// RR=32 rows/tile -> 2*16KB smem double buffer -> 6 CTAs/SM.
// Per tile: staged regs -> smem, sync, issue next tile's LDGs, walk diagonals.
// ---------------------------------------------------------------------------
__global__ void __launch_bounds__(256) tcl_diag_kernel(const float* __restrict__ x) {
    extern __shared__ float buf[];   // 2 * RR*EE floats = 32 KB

    const int b   = blockIdx.y;
    const int tid = threadIdx.x;
    const float* xb = x + (size_t)b * TT * EE;

    const int k0 = blockIdx.x * TPC;
    const int k1 = min(k0 + TPC, TILES);
    const int nk = k1 - k0;
    if (nk <= 0) return;

    float4 reg[4];

    // Prefetch tile k0 into registers (rows >= TT zero-filled).
    {
        const int r0 = k0 * RR;
        #pragma unroll
        for (int u = 0; u < 4; ++u) {
            int v    = tid + u * 256;
            int row  = v >> 5;       // / (EE/4)
            int colv = v & 31;       // % (EE/4)
            int gr   = r0 + row;
            reg[u] = (gr < TT)
                   ? __ldg((const float4*)(xb + (size_t)gr * EE) + colv)
                   : make_float4(0.f, 0.f, 0.f, 0.f);
        }
    }

    for (int kk = 0; kk < nk; ++kk) {
        float* cur = buf + (kk & 1) * (RR * EE);

        // Stage prefetched registers into the current smem buffer.
        #pragma unroll
        for (int u = 0; u < 4; ++u) {
            ((float4*)cur)[tid + u * 256] = reg[u];
        }
        __syncthreads();

        // Issue next tile's global loads immediately — DRAM busy during compute.
        if (kk + 1 < nk) {
            const int r0n = (k0 + kk + 1) * RR;
            #pragma unroll
            for (int u = 0; u < 4; ++u) {
                int v    = tid + u * 256;
                int row  = v >> 5;
                int colv = v & 31;
                int gr   = r0n + row;
                reg[u] = (gr < TT)
                       ? __ldg((const float4*)(xb + (size_t)gr * EE) + colv)
                       : make_float4(0.f, 0.f, 0.f, 0.f);
            }
        }

        // Diagonal walk: thread d owns group t = r0 + d within this tile.
        // cur[i*EE + (d-i)]: lanes d..d+31 at fixed i hit consecutive
        // addresses -> conflict-free.
        const int r0 = (k0 + kk) * RR;
        const int d  = tid;
        if (d < RR + EE - 1) {                     // 159 diagonals
            const int t    = r0 + d;
            const int tmax = min(r0 + RR, TT) - 1 + (EE - 1);
            if (t <= tmax) {
                const int i_lo = max(0, d - (EE - 1));
                const int i_hi = min(RR - 1, d);
                float s1 = 0.0f, s2 = 0.0f;
                #pragma unroll 4
                for (int i = i_lo; i <= i_hi; ++i) {
                    float v = cur[i * EE + (d - i)];
                    s1 += v;
                    s2 = fmaf(v, v, s2);
                }
                atomicAdd(&g_S1[b * LL + t], s1);
                atomicAdd(&g_S2[b * LL + t], s2);
            }
        }
        // Next iteration's post-STS sync orders the 2-apart buffer reuse.
    }
}

// ---------------------------------------------------------------------------
// Kernel 2: var = S2/c - (S1/c)^2, mean over (b,t), * 0.1.
// One float4 per thread from each array (max MLP, no loop), then RESET the
// scratch (fire-and-forget stores) so the next run starts clean. Last block
// (ticket) drains g_acc and writes out[0] directly.
// ---------------------------------------------------------------------------
__global__ void __launch_bounds__(256) tcl_finalize_kernel(float* __restrict__ out) {
    __shared__ float red[8];
    const int i = blockIdx.x * blockDim.x + threadIdx.x;   // < BB*LL/4
    float4 s1v = ((const float4*)g_S1)[i];
    float4 s2v = ((const float4*)g_S2)[i];

    // Reset for next run/replay (stores drain while we reduce).
    float4 z = make_float4(0.f, 0.f, 0.f, 0.f);
    ((float4*)g_S1)[i] = z;
    ((float4*)g_S2)[i] = z;

    float local = 0.0f;
    const int g0 = i * 4;
    #pragma unroll
    for (int j = 0; j < 4; ++j) {
        int t  = (g0 + j) & (LL - 1);              // LL is a power of two
        int ci = min(min(t + 1, EE), LL - t);
        float inv_c = 1.0f / (float)ci;
        float s1 = (j == 0) ? s1v.x : (j == 1) ? s1v.y : (j == 2) ? s1v.z : s1v.w;
        float s2 = (j == 0) ? s2v.x : (j == 1) ? s2v.y : (j == 2) ? s2v.z : s2v.w;
        float mean = s1 * inv_c;
        local += s2 * inv_c - mean * mean;
    }

    #pragma unroll
    for (int o = 16; o; o >>= 1) local += __shfl_down_sync(0xFFFFFFFFu, local, o);
    if ((threadIdx.x & 31) == 0) red[threadIdx.x >> 5] = local;
    __syncthreads();
    if (threadIdx.x < 8) {
        float v = red[threadIdx.x];
        #pragma unroll
        for (int o = 4; o; o >>= 1) v += __shfl_down_sync(0xFFu, v, o);
        if (threadIdx.x == 0) {
            atomicAdd(&g_acc, v);
            __threadfence();
            unsigned int ticket = atomicAdd(&g_cnt, 1u);
            if (ticket == gridDim.x - 1) {
                float total = atomicExch(&g_acc, 0.0f);   // read + reset
                out[0] = total * (0.1f / ((float)BB * (float)LL));
                atomicExch(&g_cnt, 0u);                   // reset ticket
            }
        }
    }
}

// ---------------------------------------------------------------------------
extern "C" void kernel_launch(void* const* d_in, const int* in_sizes, int n_in,
                              void* d_out, int out_size) {
    const float* x = (const float*)d_in[0];
    float* out = (float*)d_out;

    const int diag_smem = 2 * RR * EE * (int)sizeof(float);  // 32 KB
    cudaFuncSetAttribute(tcl_diag_kernel,
                         cudaFuncAttributeMaxDynamicSharedMemorySize, diag_smem);
    dim3 grid(CHUNKS, BB);                                 // 256 x 16 = 4096
    tcl_diag_kernel<<<grid, 256, diag_smem>>>(x);

    tcl_finalize_kernel<<<BB * LL / 4 / 256, 256>>>(out);  // 512 blocks
}